// round 4
// baseline (speedup 1.0000x reference)
#include <cuda_runtime.h>

#define N_POS    1024
#define BDIM     256
#define SPLIT    16
#define NBLK_B   (64 * SPLIT)     // 1024
#define KTOP     10
#define NWARP    (BDIM / 32)
#define STRIDE   1088             // per-batch stride for compacted lists (even, > 1024+64)
#define PAD      64

// Compacted per-batch lists (L2-resident, ~1.1 MB total) + meta. Allocation-free.
__device__ float2   g_rel[64 * STRIDE];    // (e^{-si}, disc_i), zero-padded
__device__ float2   g_non[64 * STRIDE];    // (e^{+sj}, disc_j), zero-padded
__device__ int4     g_meta[64];            // {nrel, nnon, norm_as_int, 0}
__device__ float    g_partial[NBLK_B];
__device__ int      g_count[NBLK_B];
__device__ unsigned g_ticket;              // zero-init; reset by last block each launch

// idcg prefix table: idcg(kk) = sum_{k=0}^{kk-1} 1/log2(k+2), kk = min(nrel, 10)
__constant__ float c_idcg[11] = {
    0.0f, 1.0f, 1.6309297535714574f, 2.1309297535714574f,
    2.5616063116448505f, 2.9484591188793920f, 3.3046663059874144f,
    3.6379996393207477f, 3.9534645161064764f, 4.2544945117704580f,
    4.5435593380883460f
};

// ---------------- Kernel A: per-batch compaction (once, not 16x) ----------------
__global__ __launch_bounds__(BDIM) void lambdarank_compact(
    const float* __restrict__ scores, const int* __restrict__ rels)
{
    __shared__ int sh_cntR[NWARP], sh_baseR[NWARP], sh_baseN[NWARP];
    __shared__ int sh_tot[2];

    const int b    = blockIdx.x;
    const int t    = threadIdx.x;
    const int lane = t & 31;
    const int wid  = t >> 5;
    const unsigned lt_mask = (1u << lane) - 1u;

    unsigned masks[4];
    float    sc[4];
    {
        int cr = 0;
        #pragma unroll
        for (int it = 0; it < 4; it++) {
            int p = (wid << 7) + (it << 5) + lane;
            sc[it] = scores[b * N_POS + p];
            int r  = rels[b * N_POS + p];
            unsigned m = __ballot_sync(0xffffffffu, r != 0);
            masks[it] = m;
            cr += __popc(m);
        }
        if (lane == 0) sh_cntR[wid] = cr;
    }
    __syncthreads();
    if (t == 0) {
        int aR = 0, aN = 0;
        #pragma unroll
        for (int w = 0; w < NWARP; w++) {
            sh_baseR[w] = aR; sh_baseN[w] = aN;
            aR += sh_cntR[w]; aN += 128 - sh_cntR[w];
        }
        sh_tot[0] = aR; sh_tot[1] = aN;
    }
    __syncthreads();

    // Deterministic stable scatter of (E, disc) into compacted global lists
    {
        int rb = sh_baseR[wid], nb = sh_baseN[wid];
        const size_t base = (size_t)b * STRIDE;
        #pragma unroll
        for (int it = 0; it < 4; it++) {
            int p = (wid << 7) + (it << 5) + lane;
            unsigned m = masks[it];
            bool hit = (m >> lane) & 1u;
            float E  = __expf(hit ? -sc[it] : sc[it]);
            float d  = 1.0f / __log2f((float)p + 2.0f);   // DCG discount @ position p
            float2 v = make_float2(E, d);
            int preR = __popc(m & lt_mask);
            if (hit) g_rel[base + rb + preR]          = v;
            else     g_non[base + nb + (lane - preR)] = v;
            rb += __popc(m);
            nb += 32 - __popc(m);
        }
    }

    const int nrel = sh_tot[0];
    const int nnon = sh_tot[1];

    // Zero padding: E=0 entries contribute exactly 0 in the pair loop
    if (t < PAD) {
        g_rel[(size_t)b * STRIDE + nrel + t] = make_float2(0.0f, 0.0f);
        g_non[(size_t)b * STRIDE + nnon + t] = make_float2(0.0f, 0.0f);
    }

    if (t == 0) {
        const float idcg = c_idcg[(nrel < KTOP) ? nrel : KTOP];
        const float norm = 0.69314718055994531f / (idcg + 1e-8f);  // ln2/(idcg+eps)
        g_meta[b] = make_int4(nrel, nnon, __float_as_int(norm), 0);
    }
}

// ---------------- Kernel B: pair loop + fused finalize ----------------
__global__ __launch_bounds__(BDIM) void lambdarank_pairs(float* __restrict__ out)
{
    __shared__ float2 nonS[72];              // j-chunk (<= 64 + round-up pad)
    __shared__ float  red_f[NWARP];
    __shared__ int    red_i[NWARP];
    __shared__ bool   s_last;

    const int b    = blockIdx.x >> 4;        // SPLIT = 16
    const int s    = blockIdx.x & (SPLIT - 1);
    const int t    = threadIdx.x;
    const int lane = t & 31;
    const int wid  = t >> 5;

    const int4 meta = g_meta[b];
    const int   nrel = meta.x;
    const int   nnon = meta.y;
    const float norm = __int_as_float(meta.z);

    int cntj = 0, trips = 0;
    if (nrel > 0 && nnon > 0) {
        const int chunk = (nnon + SPLIT - 1) >> 4;   // contiguous j-chunk per block
        const int j0    = s * chunk;
        cntj  = nnon - j0;
        cntj  = (cntj < 0) ? 0 : ((cntj > chunk) ? chunk : cntj);
        trips = (cntj + 3) & ~3;
        if (t < trips) {
            nonS[t] = (t < cntj) ? g_non[(size_t)b * STRIDE + j0 + t]
                                 : make_float2(0.0f, 0.0f);
        }
    }
    __syncthreads();

    float thread_sum = 0.0f;
    int   blk_count  = nrel * cntj;

    if (trips > 0) {
        const float2* relp = &g_rel[(size_t)b * STRIDE];

        for (int ibase = 0; ibase < nrel; ibase += 2 * BDIM) {
            if (ibase + (wid << 6) >= nrel) continue;    // whole-warp tail skip
            const int ia = ibase + 2 * t;                // zero-pad covers overhang
            float4 rv = *(const float4*)&relp[ia];       // coalesced LDG.128, L2 hit
            const float Ei0 = rv.x, di0 = rv.y;
            const float Ei1 = rv.z, di1 = rv.w;

            float a0 = 0.0f, a1 = 0.0f;
            #pragma unroll 4
            for (int k = 0; k < trips; k++) {
                float2 nd = nonS[k];                     // LDS.64 broadcast
                float u0 = fmaf(nd.x, Ei0, 1.0f);
                float u1 = fmaf(nd.x, Ei1, 1.0f);
                a0 = fmaf(fabsf(di0 - nd.y), __log2f(u0), a0);
                a1 = fmaf(fabsf(di1 - nd.y), __log2f(u1), a1);
            }
            thread_sum += a0 + a1;
        }
        thread_sum *= norm;
    }

    // Deterministic block reduction
    {
        float ws = thread_sum;
        #pragma unroll
        for (int o = 16; o > 0; o >>= 1) ws += __shfl_down_sync(0xffffffffu, ws, o);
        if (lane == 0) red_f[wid] = ws;
        __syncthreads();
        if (wid == 0) {
            float v2 = (lane < NWARP) ? red_f[lane] : 0.0f;
            #pragma unroll
            for (int o = 4; o > 0; o >>= 1) v2 += __shfl_down_sync(0xffffffffu, v2, o);
            if (lane == 0) {
                g_partial[blockIdx.x] = v2;
                g_count[blockIdx.x]   = blk_count;
            }
        }
    }

    // Fused finalize: last block reduces all partials in fixed order
    __threadfence();
    if (t == 0)
        s_last = (atomicAdd(&g_ticket, 1u) == (unsigned)(NBLK_B - 1));
    __syncthreads();

    if (s_last) {
        float fs = 0.0f;
        int   cs = 0;
        for (int idx = t; idx < NBLK_B; idx += BDIM) {
            fs += g_partial[idx];
            cs += g_count[idx];
        }
        #pragma unroll
        for (int o = 16; o > 0; o >>= 1) {
            fs += __shfl_down_sync(0xffffffffu, fs, o);
            cs += __shfl_down_sync(0xffffffffu, cs, o);
        }
        if (lane == 0) { red_f[wid] = fs; red_i[wid] = cs; }
        __syncthreads();
        if (t == 0) {
            float st = 0.0f; int ct = 0;
            #pragma unroll
            for (int w = 0; w < NWARP; w++) { st += red_f[w]; ct += red_i[w]; }
            out[0] = (ct > 0) ? (st / (float)ct) : 0.0f;
            g_ticket = 0;   // reset for next graph replay
        }
    }
}

extern "C" void kernel_launch(void* const* d_in, const int* in_sizes, int n_in,
                              void* d_out, int out_size)
{
    const float* scores = (const float*)d_in[0];
    const int*   rels   = (const int*)d_in[1];

    const int B = in_sizes[0] / N_POS;   // 64

    lambdarank_compact<<<B, BDIM>>>(scores, rels);
    lambdarank_pairs<<<B * SPLIT, BDIM>>>((float*)d_out);
}